// round 1
// baseline (speedup 1.0000x reference)
#include <cuda_runtime.h>
#include <cstdint>

// Problem constants (fixed shapes for this problem instance)
#define T_TOK 1024
#define HDIM  2048
#define NEXP  16
#define IDIM  1408   // routed expert intermediate
#define IS2   2816   // shared expert intermediate
#define TOPK  4

typedef unsigned long long ull;

// ---------------- scratch (device globals; no allocation allowed) ----------------
__device__ int   g_cnt[NEXP];
__device__ int   g_tok[NEXP * T_TOK];
__device__ float g_tw [NEXP * T_TOK];
__device__ int   g_tid4[T_TOK * TOPK];
__device__ float g_twk4[T_TOK * TOPK];
__device__ float g_act [NEXP * T_TOK * IDIM];   // 92 MB routed activations
__device__ float g_acts[T_TOK * IS2];           // 11.5 MB shared activations

// ---------------- packed fp32x2 helpers (sm_100+ only, PTX-only path) ----------------
#define FFMA2(d, a, b) asm("fma.rn.f32x2 %0, %1, %2, %0;" : "+l"(d) : "l"(a), "l"(b))
__device__ __forceinline__ ull pack2(float s) {
    ull d; unsigned u = __float_as_uint(s);
    asm("mov.b64 %0, {%1, %1};" : "=l"(d) : "r"(u));
    return d;
}
__device__ __forceinline__ void unpk2(float& lo, float& hi, ull s) {
    unsigned a, b;
    asm("mov.b64 {%0, %1}, %2;" : "=r"(a), "=r"(b) : "l"(s));
    lo = __uint_as_float(a); hi = __uint_as_float(b);
}
__device__ __forceinline__ float silu(float g) { return g / (1.f + expf(-g)); }

// ---------------- 1) router ----------------
__global__ void router_kernel(const float* __restrict__ x,
                              const float* __restrict__ gw,
                              const float* __restrict__ bias,
                              int* __restrict__ tid4, float* __restrict__ twk4)
{
    int t = blockIdx.x;
    int tid = threadIdx.x;            // 128 threads: 16 experts x 8 lanes
    int e = tid >> 3, r = tid & 7;
    const float4* x4 = reinterpret_cast<const float4*>(x + (size_t)t * HDIM);
    const float4* w4 = reinterpret_cast<const float4*>(gw + (size_t)e * HDIM);
    float s = 0.f;
    #pragma unroll 4
    for (int j = r; j < HDIM / 4; j += 8) {
        float4 a = x4[j], b = w4[j];
        s += a.x * b.x + a.y * b.y + a.z * b.z + a.w * b.w;
    }
    #pragma unroll
    for (int o = 4; o > 0; o >>= 1) s += __shfl_down_sync(0xffffffffu, s, o, 8);
    __shared__ float logit[NEXP];
    if (r == 0) logit[e] = s;
    __syncthreads();
    if (tid == 0) {
        float sc[NEXP], sb[NEXP];
        #pragma unroll
        for (int i = 0; i < NEXP; i++) {
            sc[i] = 1.f / (1.f + expf(-logit[i]));
            sb[i] = sc[i] + bias[i];
        }
        // group score = sum of top-2 biased scores within each group of 4
        float gsc[4];
        #pragma unroll
        for (int g = 0; g < 4; g++) {
            const float* p = sb + g * 4;
            float m1 = p[0]; int i1 = 0;
            for (int i = 1; i < 4; i++) if (p[i] > m1) { m1 = p[i]; i1 = i; }
            float m2 = -1e30f;
            for (int i = 0; i < 4; i++) if (i != i1 && p[i] > m2) m2 = p[i];
            gsc[g] = m1 + m2;
        }
        int g1 = 0; for (int g = 1; g < 4; g++) if (gsc[g] > gsc[g1]) g1 = g;
        int g2 = (g1 == 0) ? 1 : 0;
        for (int g = 0; g < 4; g++) if (g != g1 && gsc[g] > gsc[g2]) g2 = g;
        bool allow[NEXP];
        for (int i = 0; i < NEXP; i++) { int g = i >> 2; allow[i] = (g == g1 || g == g2); }
        int ids[TOPK]; float wsum = 0.f;
        for (int k = 0; k < TOPK; k++) {
            int best = 0; float bv = -1e30f;
            for (int i = 0; i < NEXP; i++)
                if (allow[i] && sb[i] > bv) { bv = sb[i]; best = i; }
            allow[best] = false;
            ids[k] = best;
            wsum += sc[best];
        }
        for (int k = 0; k < TOPK; k++) {
            tid4[t * TOPK + k] = ids[k];
            twk4[t * TOPK + k] = sc[ids[k]] / wsum;
        }
    }
}

// ---------------- 2) deterministic per-expert token lists ----------------
__global__ void build_lists(const int* __restrict__ tid4, const float* __restrict__ twk4,
                            int* __restrict__ cnt, int* __restrict__ tok, float* __restrict__ tw)
{
    int e = threadIdx.x;
    if (e >= NEXP) return;
    int c = 0;
    for (int t = 0; t < T_TOK; t++) {
        int4  id = reinterpret_cast<const int4*>(tid4)[t];
        float4 w = reinterpret_cast<const float4*>(twk4)[t];
        if (id.x == e) { tok[e * T_TOK + c] = t; tw[e * T_TOK + c] = w.x * 2.5f; c++; }
        if (id.y == e) { tok[e * T_TOK + c] = t; tw[e * T_TOK + c] = w.y * 2.5f; c++; }
        if (id.z == e) { tok[e * T_TOK + c] = t; tw[e * T_TOK + c] = w.z * 2.5f; c++; }
        if (id.w == e) { tok[e * T_TOK + c] = t; tw[e * T_TOK + c] = w.w * 2.5f; c++; }
    }
    cnt[e] = c;
}

// ---------------- 3) gate_up grouped GEMM + silu (routed & shared) ----------------
// block tile 128(M) x 64(N-pairs g,u), BK=16. thread micro: 8m x 4n for g and u.
__global__ void __launch_bounds__(256)
gu_gemm(const float* __restrict__ X, const float* __restrict__ W,
        float* __restrict__ ACT,
        const int* __restrict__ tok, const float* __restrict__ tw,
        const int* __restrict__ cnt, int Iw)
{
    const int BM = 128, BN = 64, BK = 16;
    int e = blockIdx.z;
    int cn = cnt ? cnt[e] : T_TOK;
    int m0 = blockIdx.y * BM;
    if (m0 >= cn) return;
    int n0 = blockIdx.x * BN;
    int ldW = 2 * Iw;
    const float* We  = W + (size_t)e * HDIM * ldW;
    const int* tokE  = tok ? tok + e * T_TOK : nullptr;
    const float* twE = tw ? tw + e * T_TOK : nullptr;
    float* actE = ACT + (size_t)e * T_TOK * Iw;

    __shared__ __align__(16) float As[BK][BM];
    __shared__ __align__(16) float Bgs[BK][BN];
    __shared__ __align__(16) float Bus[BK][BN];

    int tid = threadIdx.x;
    int am = tid >> 1, ak = (tid & 1) * 8;
    int as = m0 + am;
    bool av = as < cn;
    int arow = av ? (tokE ? tokE[as] : as) : 0;
    const float* Ap = X + (size_t)arow * HDIM + ak;
    int bk = tid >> 4, bj = (tid & 15) * 4;
    const float* Bgp = We + (size_t)bk * ldW + n0 + bj;

    int ty = tid >> 4, tx = tid & 15;
    int mr = ty * 8, nr = tx * 4;

    ull ag[4][4], au[4][4];
    #pragma unroll
    for (int i = 0; i < 4; i++)
        #pragma unroll
        for (int j = 0; j < 4; j++) { ag[i][j] = 0ull; au[i][j] = 0ull; }

    float4 z4 = make_float4(0.f, 0.f, 0.f, 0.f);
    float4 pa0 = av ? *(const float4*)(Ap)     : z4;
    float4 pa1 = av ? *(const float4*)(Ap + 4) : z4;
    float4 pg  = *(const float4*)(Bgp);
    float4 pu  = *(const float4*)(Bgp + Iw);

    const int NK = HDIM / BK;
    #pragma unroll 1
    for (int kt = 0; kt < NK; kt++) {
        As[ak + 0][am] = pa0.x; As[ak + 1][am] = pa0.y; As[ak + 2][am] = pa0.z; As[ak + 3][am] = pa0.w;
        As[ak + 4][am] = pa1.x; As[ak + 5][am] = pa1.y; As[ak + 6][am] = pa1.z; As[ak + 7][am] = pa1.w;
        *(float4*)&Bgs[bk][bj] = pg;
        *(float4*)&Bus[bk][bj] = pu;
        __syncthreads();
        if (kt + 1 < NK) {
            const float* An = Ap + (kt + 1) * BK;
            pa0 = av ? *(const float4*)(An)     : z4;
            pa1 = av ? *(const float4*)(An + 4) : z4;
            const float* Bn = Bgp + (size_t)(kt + 1) * BK * ldW;
            pg = *(const float4*)(Bn);
            pu = *(const float4*)(Bn + Iw);
        }
        #pragma unroll
        for (int kk = 0; kk < BK; kk++) {
            ull a[4];
            #pragma unroll
            for (int i = 0; i < 4; i++) a[i] = *(const ull*)&As[kk][mr + 2 * i];
            float4 g4 = *(const float4*)&Bgs[kk][nr];
            float4 u4 = *(const float4*)&Bus[kk][nr];
            ull bg[4], bu[4];
            bg[0] = pack2(g4.x); bg[1] = pack2(g4.y); bg[2] = pack2(g4.z); bg[3] = pack2(g4.w);
            bu[0] = pack2(u4.x); bu[1] = pack2(u4.y); bu[2] = pack2(u4.z); bu[3] = pack2(u4.w);
            #pragma unroll
            for (int i = 0; i < 4; i++)
                #pragma unroll
                for (int j = 0; j < 4; j++) { FFMA2(ag[i][j], a[i], bg[j]); FFMA2(au[i][j], a[i], bu[j]); }
        }
        __syncthreads();
    }

    #pragma unroll
    for (int i = 0; i < 4; i++) {
        int s0 = m0 + mr + 2 * i, s1 = s0 + 1;
        bool v0 = s0 < cn, v1 = s1 < cn;
        float w0 = 1.f, w1 = 1.f;
        if (twE) { if (v0) w0 = twE[s0]; if (v1) w1 = twE[s1]; }
        #pragma unroll
        for (int j = 0; j < 4; j++) {
            float glo, ghi, ulo, uhi;
            unpk2(glo, ghi, ag[i][j]);
            unpk2(ulo, uhi, au[i][j]);
            int col = n0 + nr + j;
            if (v0) actE[(size_t)s0 * Iw + col] = silu(glo) * ulo * w0;
            if (v1) actE[(size_t)s1 * Iw + col] = silu(ghi) * uhi * w1;
        }
    }
}

// ---------------- 4) down-proj grouped GEMM (routed: atomicAdd scatter; shared: store) ----------------
// block tile 128(M) x 128(N), BK=16. thread micro: 8m x 8n.
__global__ void __launch_bounds__(256)
down_gemm(const float* __restrict__ A, const float* __restrict__ W,
          float* __restrict__ OUT,
          const int* __restrict__ tok, const int* __restrict__ cnt,
          int K, int accumulate)
{
    const int BM = 128, BN = 128, BK = 16;
    int e = blockIdx.z;
    int cn = cnt ? cnt[e] : T_TOK;
    int m0 = blockIdx.y * BM;
    if (m0 >= cn) return;
    int n0 = blockIdx.x * BN;
    const float* Ae = A + (size_t)e * T_TOK * K;
    const float* We = W + (size_t)e * K * HDIM;
    const int* tokE = tok ? tok + e * T_TOK : nullptr;

    __shared__ __align__(16) float As[BK][BM];
    __shared__ __align__(16) float Bs[BK][BN];

    int tid = threadIdx.x;
    int am = tid >> 1, ak = (tid & 1) * 8;
    int as = m0 + am;
    bool av = as < cn;
    const float* Ap = Ae + (size_t)(av ? as : 0) * K + ak;
    int bk = tid >> 4, bj = (tid & 15) * 8;
    const float* Bp = We + (size_t)bk * HDIM + n0 + bj;

    int ty = tid >> 4, tx = tid & 15;
    int mr = ty * 8, nr = tx * 8;

    ull acc[4][8];
    #pragma unroll
    for (int i = 0; i < 4; i++)
        #pragma unroll
        for (int j = 0; j < 8; j++) acc[i][j] = 0ull;

    float4 z4 = make_float4(0.f, 0.f, 0.f, 0.f);
    float4 pa0 = av ? *(const float4*)(Ap)     : z4;
    float4 pa1 = av ? *(const float4*)(Ap + 4) : z4;
    float4 pb0 = *(const float4*)(Bp);
    float4 pb1 = *(const float4*)(Bp + 4);

    const int NK = K / BK;
    #pragma unroll 1
    for (int kt = 0; kt < NK; kt++) {
        As[ak + 0][am] = pa0.x; As[ak + 1][am] = pa0.y; As[ak + 2][am] = pa0.z; As[ak + 3][am] = pa0.w;
        As[ak + 4][am] = pa1.x; As[ak + 5][am] = pa1.y; As[ak + 6][am] = pa1.z; As[ak + 7][am] = pa1.w;
        *(float4*)&Bs[bk][bj]     = pb0;
        *(float4*)&Bs[bk][bj + 4] = pb1;
        __syncthreads();
        if (kt + 1 < NK) {
            const float* An = Ap + (kt + 1) * BK;
            pa0 = av ? *(const float4*)(An)     : z4;
            pa1 = av ? *(const float4*)(An + 4) : z4;
            const float* Bn = Bp + (size_t)(kt + 1) * BK * HDIM;
            pb0 = *(const float4*)(Bn);
            pb1 = *(const float4*)(Bn + 4);
        }
        #pragma unroll
        for (int kk = 0; kk < BK; kk++) {
            ull a[4];
            #pragma unroll
            for (int i = 0; i < 4; i++) a[i] = *(const ull*)&As[kk][mr + 2 * i];
            float4 b0 = *(const float4*)&Bs[kk][nr];
            float4 b1 = *(const float4*)&Bs[kk][nr + 4];
            ull bb[8];
            bb[0] = pack2(b0.x); bb[1] = pack2(b0.y); bb[2] = pack2(b0.z); bb[3] = pack2(b0.w);
            bb[4] = pack2(b1.x); bb[5] = pack2(b1.y); bb[6] = pack2(b1.z); bb[7] = pack2(b1.w);
            #pragma unroll
            for (int i = 0; i < 4; i++)
                #pragma unroll
                for (int j = 0; j < 8; j++) FFMA2(acc[i][j], a[i], bb[j]);
        }
        __syncthreads();
    }

    #pragma unroll
    for (int i = 0; i < 4; i++) {
        int s0 = m0 + mr + 2 * i, s1 = s0 + 1;
        bool v0 = s0 < cn, v1 = s1 < cn;
        int r0 = v0 ? (tokE ? tokE[s0] : s0) : 0;
        int r1 = v1 ? (tokE ? tokE[s1] : s1) : 0;
        float* o0 = OUT + (size_t)r0 * HDIM + n0 + nr;
        float* o1 = OUT + (size_t)r1 * HDIM + n0 + nr;
        #pragma unroll
        for (int j = 0; j < 8; j++) {
            float lo, hi;
            unpk2(lo, hi, acc[i][j]);
            if (accumulate) {
                if (v0) atomicAdd(o0 + j, lo);
                if (v1) atomicAdd(o1 + j, hi);
            } else {
                if (v0) o0[j] = lo;
                if (v1) o1[j] = hi;
            }
        }
    }
}

// ---------------- launch ----------------
extern "C" void kernel_launch(void* const* d_in, const int* in_sizes, int n_in,
                              void* d_out, int out_size)
{
    const float* x    = (const float*)d_in[0];
    const float* gw   = (const float*)d_in[1];
    const float* bias = (const float*)d_in[2];
    const float* wgu  = (const float*)d_in[3];
    const float* wdn  = (const float*)d_in[4];
    const float* sgu  = (const float*)d_in[5];
    const float* sdn  = (const float*)d_in[6];
    float* out = (float*)d_out;

    void *p_cnt, *p_tok, *p_tw, *p_t4, *p_w4, *p_act, *p_acts;
    cudaGetSymbolAddress(&p_cnt,  g_cnt);
    cudaGetSymbolAddress(&p_tok,  g_tok);
    cudaGetSymbolAddress(&p_tw,   g_tw);
    cudaGetSymbolAddress(&p_t4,   g_tid4);
    cudaGetSymbolAddress(&p_w4,   g_twk4);
    cudaGetSymbolAddress(&p_act,  g_act);
    cudaGetSymbolAddress(&p_acts, g_acts);

    // 1) router: token -> (top-4 expert ids, renormalized weights)
    router_kernel<<<T_TOK, 128>>>(x, gw, bias, (int*)p_t4, (float*)p_w4);
    // 2) deterministic per-expert token lists (2.5x routed scaling folded into weights)
    build_lists<<<1, 16>>>((const int*)p_t4, (const float*)p_w4,
                           (int*)p_cnt, (int*)p_tok, (float*)p_tw);
    // 3) shared gate_up + silu
    gu_gemm<<<dim3(IS2 / 64, T_TOK / 128, 1), 256>>>(
        x, sgu, (float*)p_acts, nullptr, nullptr, nullptr, IS2);
    // 4) routed gate_up + silu (gathered, weight-scaled)
    gu_gemm<<<dim3(IDIM / 64, T_TOK / 128, NEXP), 256>>>(
        x, wgu, (float*)p_act, (const int*)p_tok, (const float*)p_tw,
        (const int*)p_cnt, IDIM);
    // 5) shared down-proj: initializes out
    down_gemm<<<dim3(HDIM / 128, T_TOK / 128, 1), 256>>>(
        (const float*)p_acts, sdn, out, nullptr, nullptr, IS2, 0);
    // 6) routed down-proj: atomicAdd scatter into out
    down_gemm<<<dim3(HDIM / 128, T_TOK / 128, NEXP), 256>>>(
        (const float*)p_act, wdn, out, (const int*)p_tok, (const int*)p_cnt, IDIM, 1);
}

// round 3
// speedup vs baseline: 2.2125x; 2.2125x over previous
#include <cuda_runtime.h>
#include <cstdint>

#define T_TOK 1024
#define HDIM  2048
#define NEXP  16
#define IDIM  1408
#define SI    2816
#define TOPK  4

typedef unsigned long long ull;
typedef unsigned int u32;

// ---------------- scratch (device globals; no allocation allowed) ----------------
__device__ int   g_cnt[NEXP];
__device__ int   g_tok[NEXP * T_TOK];
__device__ float g_tw [NEXP * T_TOK];
__device__ int   g_tid4[T_TOK * TOPK];
__device__ float g_twk4[T_TOK * TOPK];
__device__ float g_act [(size_t)NEXP * T_TOK * IDIM];   // routed activations (slot-major)
__device__ float g_acts[(size_t)T_TOK * SI];            // shared activations

// ---------------- helpers ----------------
__device__ __forceinline__ float to_tf32(float f) {
    u32 u;
    asm("cvt.rna.tf32.f32 %0, %1;" : "=r"(u) : "f"(f));
    return __uint_as_float(u);
}
__device__ __forceinline__ float4 tf32_4(float4 v) {
    v.x = to_tf32(v.x); v.y = to_tf32(v.y); v.z = to_tf32(v.z); v.w = to_tf32(v.w);
    return v;
}
__device__ __forceinline__ void mma8(float* d, const u32* a, const u32* b) {
    asm volatile(
        "mma.sync.aligned.m16n8k8.row.col.f32.tf32.tf32.f32 "
        "{%0,%1,%2,%3}, {%4,%5,%6,%7}, {%8,%9}, {%0,%1,%2,%3};"
        : "+f"(d[0]), "+f"(d[1]), "+f"(d[2]), "+f"(d[3])
        : "r"(a[0]), "r"(a[1]), "r"(a[2]), "r"(a[3]), "r"(b[0]), "r"(b[1]));
}
__device__ __forceinline__ float silu_f(float g) { return g / (1.f + expf(-g)); }

// ---------------- router (exact fp32) ----------------
__global__ void router_kernel(const float* __restrict__ x,
                              const float* __restrict__ gw,
                              const float* __restrict__ bias,
                              int* __restrict__ tid4, float* __restrict__ twk4)
{
    int t = blockIdx.x;
    int tid = threadIdx.x;            // 128 threads: 16 experts x 8 lanes
    int e = tid >> 3, r = tid & 7;
    const float4* x4 = reinterpret_cast<const float4*>(x + (size_t)t * HDIM);
    const float4* w4 = reinterpret_cast<const float4*>(gw + (size_t)e * HDIM);
    float s = 0.f;
    #pragma unroll 4
    for (int j = r; j < HDIM / 4; j += 8) {
        float4 a = x4[j], b = w4[j];
        s += a.x * b.x + a.y * b.y + a.z * b.z + a.w * b.w;
    }
    #pragma unroll
    for (int o = 4; o > 0; o >>= 1) s += __shfl_down_sync(0xffffffffu, s, o, 8);
    __shared__ float logit[NEXP];
    if (r == 0) logit[e] = s;
    __syncthreads();
    if (tid == 0) {
        float sc[NEXP], sb[NEXP];
        #pragma unroll
        for (int i = 0; i < NEXP; i++) {
            sc[i] = 1.f / (1.f + expf(-logit[i]));
            sb[i] = sc[i] + bias[i];
        }
        float gsc[4];
        #pragma unroll
        for (int g = 0; g < 4; g++) {
            const float* p = sb + g * 4;
            float m1 = p[0]; int i1 = 0;
            for (int i = 1; i < 4; i++) if (p[i] > m1) { m1 = p[i]; i1 = i; }
            float m2 = -1e30f;
            for (int i = 0; i < 4; i++) if (i != i1 && p[i] > m2) m2 = p[i];
            gsc[g] = m1 + m2;
        }
        int g1 = 0; for (int g = 1; g < 4; g++) if (gsc[g] > gsc[g1]) g1 = g;
        int g2 = (g1 == 0) ? 1 : 0;
        for (int g = 0; g < 4; g++) if (g != g1 && gsc[g] > gsc[g2]) g2 = g;
        bool allow[NEXP];
        for (int i = 0; i < NEXP; i++) { int g = i >> 2; allow[i] = (g == g1 || g == g2); }
        int ids[TOPK]; float wsum = 0.f;
        for (int k = 0; k < TOPK; k++) {
            int best = 0; float bv = -1e30f;
            for (int i = 0; i < NEXP; i++)
                if (allow[i] && sb[i] > bv) { bv = sb[i]; best = i; }
            allow[best] = false;
            ids[k] = best;
            wsum += sc[best];
        }
        for (int k = 0; k < TOPK; k++) {
            tid4[t * TOPK + k] = ids[k];
            twk4[t * TOPK + k] = sc[ids[k]] / wsum;
        }
    }
}

// ---------------- deterministic per-expert token lists ----------------
__global__ void build_lists(const int* __restrict__ tid4, const float* __restrict__ twk4,
                            int* __restrict__ cnt, int* __restrict__ tok, float* __restrict__ tw)
{
    int e = threadIdx.x;
    if (e >= NEXP) return;
    int c = 0;
    for (int t = 0; t < T_TOK; t++) {
        int4  id = reinterpret_cast<const int4*>(tid4)[t];
        float4 w = reinterpret_cast<const float4*>(twk4)[t];
        if (id.x == e) { tok[e * T_TOK + c] = t; tw[e * T_TOK + c] = w.x * 2.5f; c++; }
        if (id.y == e) { tok[e * T_TOK + c] = t; tw[e * T_TOK + c] = w.y * 2.5f; c++; }
        if (id.z == e) { tok[e * T_TOK + c] = t; tw[e * T_TOK + c] = w.z * 2.5f; c++; }
        if (id.w == e) { tok[e * T_TOK + c] = t; tw[e * T_TOK + c] = w.w * 2.5f; c++; }
    }
    cnt[e] = c;
}

// =====================================================================
// gate_up GEMM via mma.sync tf32: per CTA computes act[128 x 64]
//   g = X Wg, u = X Wu, act = silu(g)*u*w
// A tile [128m x 32k] smem row-major stride 36 (conflict-free frags)
// B tiles [32k x 64n] smem natural stride 72 (conflict-free frags)
// 8 warps: 4 (m) x 2 (n), warp tile 32m x 32n of BOTH g and u
// =====================================================================
#define SA 36
#define SBG 72
__global__ void __launch_bounds__(256)
gu_mma(const float* __restrict__ X, const float* __restrict__ W,
       float* __restrict__ ACT,
       const int* __restrict__ tok, const float* __restrict__ tw,
       const int* __restrict__ cnt, int Iw, int K)
{
    __shared__ __align__(16) float As[128 * SA];
    __shared__ __align__(16) float Bg[32 * SBG];
    __shared__ __align__(16) float Bu[32 * SBG];
    __shared__ int   tokSm[128];
    __shared__ float twSm[128];

    int e = blockIdx.z;
    int cn = cnt ? cnt[e] : T_TOK;
    int m0 = blockIdx.y * 128;
    if (m0 >= cn) return;
    int n0 = blockIdx.x * 64;
    int ldW = 2 * Iw;
    const float* We = W + (size_t)e * K * ldW;
    float* actE = ACT + (size_t)e * T_TOK * Iw;

    int tid = threadIdx.x;
    if (tid < 128) {
        int s = m0 + tid; int a; float wv;
        if (tok) {
            const int* tokE = tok + e * T_TOK;
            const float* twE = tw + e * T_TOK;
            if (s < cn) { a = tokE[s]; wv = twE[s]; } else { a = 0; wv = 0.f; }
        } else { a = s; wv = 1.f; }
        tokSm[tid] = a; twSm[tid] = wv;
    }
    __syncthreads();

    // staging mapping
    int arow = tid >> 1, kh = (tid & 1) * 16;
    const float* aP = X + (size_t)tokSm[arow] * K + kh;
    int bk = tid >> 3, bn = (tid & 7) * 8;
    const float* gP = We + (size_t)bk * ldW + n0 + bn;
    const float* uP = gP + Iw;

    // warp mapping
    int w = tid >> 5, lane = tid & 31;
    int g = lane >> 2, t = lane & 3;
    int wm = (w & 3) * 32, wn = (w >> 2) * 32;

    float ag[2][4][4], au[2][4][4];
    #pragma unroll
    for (int i = 0; i < 2; i++)
        #pragma unroll
        for (int j = 0; j < 4; j++)
            #pragma unroll
            for (int q = 0; q < 4; q++) { ag[i][j][q] = 0.f; au[i][j][q] = 0.f; }

    float4 pa[4], pg[2], pu[2];
    #pragma unroll
    for (int i = 0; i < 4; i++) pa[i] = *(const float4*)(aP + 4 * i);
    pg[0] = *(const float4*)(gP); pg[1] = *(const float4*)(gP + 4);
    pu[0] = *(const float4*)(uP); pu[1] = *(const float4*)(uP + 4);

    const int NK = K / 32;
    for (int it = 0; it < NK; ++it) {
        // store staged tile (with tf32 rounding)
        #pragma unroll
        for (int i = 0; i < 4; i++)
            *(float4*)&As[arow * SA + kh + 4 * i] = tf32_4(pa[i]);
        *(float4*)&Bg[bk * SBG + bn]     = tf32_4(pg[0]);
        *(float4*)&Bg[bk * SBG + bn + 4] = tf32_4(pg[1]);
        *(float4*)&Bu[bk * SBG + bn]     = tf32_4(pu[0]);
        *(float4*)&Bu[bk * SBG + bn + 4] = tf32_4(pu[1]);
        __syncthreads();

        if (it + 1 < NK) {
            const float* aN = aP + (it + 1) * 32;
            #pragma unroll
            for (int i = 0; i < 4; i++) pa[i] = *(const float4*)(aN + 4 * i);
            const float* gN = gP + (size_t)(it + 1) * 32 * ldW;
            const float* uN = gN + Iw;
            pg[0] = *(const float4*)(gN); pg[1] = *(const float4*)(gN + 4);
            pu[0] = *(const float4*)(uN); pu[1] = *(const float4*)(uN + 4);
        }

        #pragma unroll
        for (int ks = 0; ks < 4; ++ks) {
            int k0 = ks * 8;
            u32 af[2][4];
            #pragma unroll
            for (int mt = 0; mt < 2; ++mt) {
                int r = wm + mt * 16 + g;
                af[mt][0] = __float_as_uint(As[r * SA + k0 + t]);
                af[mt][1] = __float_as_uint(As[(r + 8) * SA + k0 + t]);
                af[mt][2] = __float_as_uint(As[r * SA + k0 + t + 4]);
                af[mt][3] = __float_as_uint(As[(r + 8) * SA + k0 + t + 4]);
            }
            #pragma unroll
            for (int nt = 0; nt < 4; ++nt) {
                int n = wn + nt * 8 + g;
                u32 bg2[2] = { __float_as_uint(Bg[(k0 + t) * SBG + n]),
                               __float_as_uint(Bg[(k0 + t + 4) * SBG + n]) };
                u32 bu2[2] = { __float_as_uint(Bu[(k0 + t) * SBG + n]),
                               __float_as_uint(Bu[(k0 + t + 4) * SBG + n]) };
                mma8(ag[0][nt], af[0], bg2);
                mma8(ag[1][nt], af[1], bg2);
                mma8(au[0][nt], af[0], bu2);
                mma8(au[1][nt], af[1], bu2);
            }
        }
        __syncthreads();
    }

    // epilogue: silu(g)*u*w -> act
    #pragma unroll
    for (int mt = 0; mt < 2; ++mt) {
        int l0 = wm + mt * 16 + g;
        int s0 = m0 + l0, s1 = s0 + 8;
        bool v0 = s0 < cn, v1 = s1 < cn;
        float w0 = twSm[l0], w1 = twSm[l0 + 8];
        float* o0 = actE + (size_t)s0 * Iw + n0 + wn;
        float* o1 = actE + (size_t)s1 * Iw + n0 + wn;
        #pragma unroll
        for (int nt = 0; nt < 4; ++nt) {
            int c = nt * 8 + 2 * t;
            if (v0) {
                float2 r;
                r.x = silu_f(ag[mt][nt][0]) * au[mt][nt][0] * w0;
                r.y = silu_f(ag[mt][nt][1]) * au[mt][nt][1] * w0;
                *(float2*)(o0 + c) = r;
            }
            if (v1) {
                float2 r;
                r.x = silu_f(ag[mt][nt][2]) * au[mt][nt][2] * w1;
                r.y = silu_f(ag[mt][nt][3]) * au[mt][nt][3] * w1;
                *(float2*)(o1 + c) = r;
            }
        }
    }
}

// =====================================================================
// down-proj GEMM via mma.sync tf32: C[128m x 128n] = act . W_down
// routed: atomicAdd scatter to out rows; shared: plain store
// B smem [32k x 136] natural layout (conflict-free frags)
// 8 warps: 4 (m) x 2 (n), warp tile 32m x 64n
// =====================================================================
#define SBD 136
__global__ void __launch_bounds__(256)
down_mma(const float* __restrict__ A, const float* __restrict__ W,
         float* __restrict__ OUT, const int* __restrict__ tok,
         const int* __restrict__ cnt, int K, int accum)
{
    __shared__ __align__(16) float As[128 * SA];
    __shared__ __align__(16) float Bs[32 * SBD];
    __shared__ int tokSm[128];

    int e = blockIdx.z;
    int cn = cnt ? cnt[e] : T_TOK;
    int m0 = blockIdx.y * 128;
    if (m0 >= cn) return;
    int n0 = blockIdx.x * 128;
    const float* Ae = A + (size_t)e * T_TOK * K;
    const float* Be = W + (size_t)e * K * HDIM;

    int tid = threadIdx.x;
    if (tid < 128) {
        int s = m0 + tid;
        tokSm[tid] = tok ? ((s < cn) ? tok[e * T_TOK + s] : 0) : s;
    }
    __syncthreads();

    int arow = tid >> 1, kh = (tid & 1) * 16;
    const float* aP = Ae + (size_t)(m0 + arow) * K + kh;
    int bk = tid >> 3, bn = (tid & 7) * 16;
    const float* bP = Be + (size_t)bk * HDIM + n0 + bn;

    int w = tid >> 5, lane = tid & 31;
    int g = lane >> 2, t = lane & 3;
    int wm = (w & 3) * 32, wn = (w >> 2) * 64;

    float ac[2][8][4];
    #pragma unroll
    for (int i = 0; i < 2; i++)
        #pragma unroll
        for (int j = 0; j < 8; j++)
            #pragma unroll
            for (int q = 0; q < 4; q++) ac[i][j][q] = 0.f;

    float4 pa[4], pb[4];
    #pragma unroll
    for (int i = 0; i < 4; i++) pa[i] = *(const float4*)(aP + 4 * i);
    #pragma unroll
    for (int i = 0; i < 4; i++) pb[i] = *(const float4*)(bP + 4 * i);

    const int NK = K / 32;
    for (int it = 0; it < NK; ++it) {
        #pragma unroll
        for (int i = 0; i < 4; i++)
            *(float4*)&As[arow * SA + kh + 4 * i] = tf32_4(pa[i]);
        #pragma unroll
        for (int i = 0; i < 4; i++)
            *(float4*)&Bs[bk * SBD + bn + 4 * i] = tf32_4(pb[i]);
        __syncthreads();

        if (it + 1 < NK) {
            const float* aN = aP + (it + 1) * 32;
            #pragma unroll
            for (int i = 0; i < 4; i++) pa[i] = *(const float4*)(aN + 4 * i);
            const float* bN = bP + (size_t)(it + 1) * 32 * HDIM;
            #pragma unroll
            for (int i = 0; i < 4; i++) pb[i] = *(const float4*)(bN + 4 * i);
        }

        #pragma unroll
        for (int ks = 0; ks < 4; ++ks) {
            int k0 = ks * 8;
            u32 af[2][4];
            #pragma unroll
            for (int mt = 0; mt < 2; ++mt) {
                int r = wm + mt * 16 + g;
                af[mt][0] = __float_as_uint(As[r * SA + k0 + t]);
                af[mt][1] = __float_as_uint(As[(r + 8) * SA + k0 + t]);
                af[mt][2] = __float_as_uint(As[r * SA + k0 + t + 4]);
                af[mt][3] = __float_as_uint(As[(r + 8) * SA + k0 + t + 4]);
            }
            #pragma unroll
            for (int nt = 0; nt < 8; ++nt) {
                int n = wn + nt * 8 + g;
                u32 bf2[2] = { __float_as_uint(Bs[(k0 + t) * SBD + n]),
                               __float_as_uint(Bs[(k0 + t + 4) * SBD + n]) };
                mma8(ac[0][nt], af[0], bf2);
                mma8(ac[1][nt], af[1], bf2);
            }
        }
        __syncthreads();
    }

    #pragma unroll
    for (int mt = 0; mt < 2; ++mt) {
        int l0 = wm + mt * 16 + g;
        int s0 = m0 + l0, s1 = s0 + 8;
        bool v0 = s0 < cn, v1 = s1 < cn;
        float* o0 = OUT + (size_t)tokSm[l0] * HDIM + n0 + wn;
        float* o1 = OUT + (size_t)tokSm[l0 + 8] * HDIM + n0 + wn;
        #pragma unroll
        for (int nt = 0; nt < 8; ++nt) {
            int c = nt * 8 + 2 * t;
            if (accum) {
                if (v0) { atomicAdd(o0 + c, ac[mt][nt][0]); atomicAdd(o0 + c + 1, ac[mt][nt][1]); }
                if (v1) { atomicAdd(o1 + c, ac[mt][nt][2]); atomicAdd(o1 + c + 1, ac[mt][nt][3]); }
            } else {
                if (v0) { float2 r; r.x = ac[mt][nt][0]; r.y = ac[mt][nt][1]; *(float2*)(o0 + c) = r; }
                if (v1) { float2 r; r.x = ac[mt][nt][2]; r.y = ac[mt][nt][3]; *(float2*)(o1 + c) = r; }
            }
        }
    }
}

// ---------------- launch ----------------
extern "C" void kernel_launch(void* const* d_in, const int* in_sizes, int n_in,
                              void* d_out, int out_size)
{
    const float* x    = (const float*)d_in[0];
    const float* gw   = (const float*)d_in[1];
    const float* bias = (const float*)d_in[2];
    const float* wgu  = (const float*)d_in[3];
    const float* wdn  = (const float*)d_in[4];
    const float* sgu  = (const float*)d_in[5];
    const float* sdn  = (const float*)d_in[6];
    float* out = (float*)d_out;

    void *p_cnt, *p_tok, *p_tw, *p_t4, *p_w4, *p_act, *p_acts;
    cudaGetSymbolAddress(&p_cnt,  g_cnt);
    cudaGetSymbolAddress(&p_tok,  g_tok);
    cudaGetSymbolAddress(&p_tw,   g_tw);
    cudaGetSymbolAddress(&p_t4,   g_tid4);
    cudaGetSymbolAddress(&p_w4,   g_twk4);
    cudaGetSymbolAddress(&p_act,  g_act);
    cudaGetSymbolAddress(&p_acts, g_acts);

    // 1) router + deterministic dispatch lists
    router_kernel<<<T_TOK, 128>>>(x, gw, bias, (int*)p_t4, (float*)p_w4);
    build_lists<<<1, 16>>>((const int*)p_t4, (const float*)p_w4,
                           (int*)p_cnt, (int*)p_tok, (float*)p_tw);

    // 2) gate_up + silu (tensor cores via mma.sync tf32)
    gu_mma<<<dim3(SI / 64, T_TOK / 128, 1), 256>>>(
        x, sgu, (float*)p_acts, nullptr, nullptr, nullptr, SI, HDIM);
    gu_mma<<<dim3(IDIM / 64, T_TOK / 128, NEXP), 256>>>(
        x, wgu, (float*)p_act, (const int*)p_tok, (const float*)p_tw,
        (const int*)p_cnt, IDIM, HDIM);

    // 3) down-proj: shared writes out (init), routed accumulates
    down_mma<<<dim3(HDIM / 128, T_TOK / 128, 1), 256>>>(
        (const float*)p_acts, sdn, out, nullptr, nullptr, SI, 0);
    down_mma<<<dim3(HDIM / 128, T_TOK / 128, NEXP), 256>>>(
        (const float*)p_act, wdn, out, (const int*)p_tok,
        (const int*)p_cnt, IDIM, 1);
}

// round 4
// speedup vs baseline: 2.5085x; 1.1338x over previous
#include <cuda_runtime.h>
#include <cstdint>

#define T_TOK 1024
#define HDIM  2048
#define NEXP  16
#define IDIM  1408
#define SI    2816
#define TOPK  4

typedef unsigned long long ull;
typedef unsigned int u32;

// ---------------- scratch (device globals; no allocation allowed) ----------------
__device__ int   g_cnt[NEXP];
__device__ int   g_tok[NEXP * T_TOK];
__device__ float g_tw [NEXP * T_TOK];
__device__ int   g_tid4[T_TOK * TOPK];
__device__ float g_twk4[T_TOK * TOPK];
__device__ float g_act [(size_t)NEXP * T_TOK * IDIM];   // routed activations (slot-major)
__device__ float g_acts[(size_t)T_TOK * SI];            // shared activations

// ---------------- helpers ----------------
__device__ __forceinline__ float to_tf32(float f) {
    u32 u;
    asm("cvt.rna.tf32.f32 %0, %1;" : "=r"(u) : "f"(f));
    return __uint_as_float(u);
}
__device__ __forceinline__ float4 tf32_4(float4 v) {
    v.x = to_tf32(v.x); v.y = to_tf32(v.y); v.z = to_tf32(v.z); v.w = to_tf32(v.w);
    return v;
}
__device__ __forceinline__ void mma8(float* d, const u32* a, const u32* b) {
    asm volatile(
        "mma.sync.aligned.m16n8k8.row.col.f32.tf32.tf32.f32 "
        "{%0,%1,%2,%3}, {%4,%5,%6,%7}, {%8,%9}, {%0,%1,%2,%3};"
        : "+f"(d[0]), "+f"(d[1]), "+f"(d[2]), "+f"(d[3])
        : "r"(a[0]), "r"(a[1]), "r"(a[2]), "r"(a[3]), "r"(b[0]), "r"(b[1]));
}
__device__ __forceinline__ float silu_f(float g) { return g / (1.f + expf(-g)); }

// ---------------- router (exact fp32) ----------------
__global__ void router_kernel(const float* __restrict__ x,
                              const float* __restrict__ gw,
                              const float* __restrict__ bias,
                              int* __restrict__ tid4, float* __restrict__ twk4)
{
    int t = blockIdx.x;
    int tid = threadIdx.x;            // 128 threads: 16 experts x 8 lanes
    int e = tid >> 3, r = tid & 7;
    const float4* x4 = reinterpret_cast<const float4*>(x + (size_t)t * HDIM);
    const float4* w4 = reinterpret_cast<const float4*>(gw + (size_t)e * HDIM);
    float s = 0.f;
    #pragma unroll 4
    for (int j = r; j < HDIM / 4; j += 8) {
        float4 a = x4[j], b = w4[j];
        s += a.x * b.x + a.y * b.y + a.z * b.z + a.w * b.w;
    }
    #pragma unroll
    for (int o = 4; o > 0; o >>= 1) s += __shfl_down_sync(0xffffffffu, s, o, 8);
    __shared__ float logit[NEXP];
    if (r == 0) logit[e] = s;
    __syncthreads();
    if (tid == 0) {
        float sc[NEXP], sb[NEXP];
        #pragma unroll
        for (int i = 0; i < NEXP; i++) {
            sc[i] = 1.f / (1.f + expf(-logit[i]));
            sb[i] = sc[i] + bias[i];
        }
        float gsc[4];
        #pragma unroll
        for (int g = 0; g < 4; g++) {
            const float* p = sb + g * 4;
            float m1 = p[0]; int i1 = 0;
            for (int i = 1; i < 4; i++) if (p[i] > m1) { m1 = p[i]; i1 = i; }
            float m2 = -1e30f;
            for (int i = 0; i < 4; i++) if (i != i1 && p[i] > m2) m2 = p[i];
            gsc[g] = m1 + m2;
        }
        int g1 = 0; for (int g = 1; g < 4; g++) if (gsc[g] > gsc[g1]) g1 = g;
        int g2 = (g1 == 0) ? 1 : 0;
        for (int g = 0; g < 4; g++) if (g != g1 && gsc[g] > gsc[g2]) g2 = g;
        bool allow[NEXP];
        for (int i = 0; i < NEXP; i++) { int g = i >> 2; allow[i] = (g == g1 || g == g2); }
        int ids[TOPK]; float wsum = 0.f;
        for (int k = 0; k < TOPK; k++) {
            int best = 0; float bv = -1e30f;
            for (int i = 0; i < NEXP; i++)
                if (allow[i] && sb[i] > bv) { bv = sb[i]; best = i; }
            allow[best] = false;
            ids[k] = best;
            wsum += sc[best];
        }
        for (int k = 0; k < TOPK; k++) {
            tid4[t * TOPK + k] = ids[k];
            twk4[t * TOPK + k] = sc[ids[k]] / wsum;
        }
    }
}

// ---------------- deterministic per-expert token lists ----------------
__global__ void build_lists(const int* __restrict__ tid4, const float* __restrict__ twk4,
                            int* __restrict__ cnt, int* __restrict__ tok, float* __restrict__ tw)
{
    int e = threadIdx.x;
    if (e >= NEXP) return;
    int c = 0;
    for (int t = 0; t < T_TOK; t++) {
        int4  id = reinterpret_cast<const int4*>(tid4)[t];
        float4 w = reinterpret_cast<const float4*>(twk4)[t];
        if (id.x == e) { tok[e * T_TOK + c] = t; tw[e * T_TOK + c] = w.x * 2.5f; c++; }
        if (id.y == e) { tok[e * T_TOK + c] = t; tw[e * T_TOK + c] = w.y * 2.5f; c++; }
        if (id.z == e) { tok[e * T_TOK + c] = t; tw[e * T_TOK + c] = w.z * 2.5f; c++; }
        if (id.w == e) { tok[e * T_TOK + c] = t; tw[e * T_TOK + c] = w.w * 2.5f; c++; }
    }
    cnt[e] = c;
}

// =====================================================================
// gate_up GEMM via mma.sync tf32: CTA tile 128m x (128 g-cols + 128 u-cols)
// 8 warps = 2m x 4n; warp tile 64m x (32g + 32u). act = silu(g)*u*w
// A smem [128][36]; Bg/Bu smem [32][136]; all frag/staging accesses conflict-free.
// =====================================================================
#define SA 36
#define SB 136
#define GU_DYN ((128 * SA + 2 * 32 * SB + 256) * 4)
__global__ void __launch_bounds__(256)
gu_mma(const float* __restrict__ X, const float* __restrict__ W,
       float* __restrict__ ACT,
       const int* __restrict__ tok, const float* __restrict__ tw,
       const int* __restrict__ cnt, int Iw, int K)
{
    extern __shared__ float smf[];
    float* As = smf;                       // [128][SA]
    float* Bg = As + 128 * SA;             // [32][SB]
    float* Bu = Bg + 32 * SB;              // [32][SB]
    int*   tokSm = (int*)(Bu + 32 * SB);   // [128]
    float* twSm  = (float*)(tokSm + 128);  // [128]

    int e = blockIdx.z;
    int cn = cnt ? cnt[e] : T_TOK;
    int m0 = blockIdx.y * 128;
    if (m0 >= cn) return;
    int n0 = blockIdx.x * 128;
    int ldW = 2 * Iw;
    const float* We = W + (size_t)e * K * ldW;
    float* actE = ACT + (size_t)e * T_TOK * Iw;

    int tid = threadIdx.x;
    if (tid < 128) {
        int s = m0 + tid; int a; float wv;
        if (tok) {
            const int* tokE = tok + e * T_TOK;
            const float* twE = tw + e * T_TOK;
            if (s < cn) { a = tokE[s]; wv = twE[s]; } else { a = 0; wv = 0.f; }
        } else { a = s; wv = 1.f; }
        tokSm[tid] = a; twSm[tid] = wv;
    }
    __syncthreads();

    // staging mapping: A row per thread-pair; B 4-float interleaved quads
    int arow = tid >> 1, kh = (tid & 1) * 16;
    const float* aP = X + (size_t)tokSm[arow] * K + kh;
    int bk = tid >> 3, bc = (tid & 7) * 4;
    const float* gP = We + (size_t)bk * ldW + n0 + bc;
    const float* uP = gP + Iw;

    // warp mapping: 2m x 4n
    int w = tid >> 5, lane = tid & 31;
    int g = lane >> 2, t = lane & 3;
    int wm = (w & 1) * 64, wn = (w >> 1) * 32;

    float ag[4][4][4], au[4][4][4];
    #pragma unroll
    for (int i = 0; i < 4; i++)
        #pragma unroll
        for (int j = 0; j < 4; j++)
            #pragma unroll
            for (int q = 0; q < 4; q++) { ag[i][j][q] = 0.f; au[i][j][q] = 0.f; }

    float4 pa[4], pg[4], pu[4];
    #pragma unroll
    for (int i = 0; i < 4; i++) {
        pa[i] = *(const float4*)(aP + 4 * i);
        pg[i] = *(const float4*)(gP + 32 * i);
        pu[i] = *(const float4*)(uP + 32 * i);
    }

    const int NK = K / 32;
    for (int it = 0; it < NK; ++it) {
        #pragma unroll
        for (int i = 0; i < 4; i++) {
            *(float4*)&As[arow * SA + kh + 4 * i]  = tf32_4(pa[i]);
            *(float4*)&Bg[bk * SB + bc + 32 * i]   = tf32_4(pg[i]);
            *(float4*)&Bu[bk * SB + bc + 32 * i]   = tf32_4(pu[i]);
        }
        __syncthreads();

        if (it + 1 < NK) {
            const float* aN = aP + (it + 1) * 32;
            const float* gN = gP + (size_t)(it + 1) * 32 * ldW;
            const float* uN = gN + Iw;
            #pragma unroll
            for (int i = 0; i < 4; i++) {
                pa[i] = *(const float4*)(aN + 4 * i);
                pg[i] = *(const float4*)(gN + 32 * i);
                pu[i] = *(const float4*)(uN + 32 * i);
            }
        }

        #pragma unroll
        for (int ks = 0; ks < 4; ++ks) {
            int k0 = ks * 8;
            u32 af[4][4];
            #pragma unroll
            for (int mt = 0; mt < 4; ++mt) {
                int r = wm + mt * 16 + g;
                af[mt][0] = __float_as_uint(As[r * SA + k0 + t]);
                af[mt][1] = __float_as_uint(As[(r + 8) * SA + k0 + t]);
                af[mt][2] = __float_as_uint(As[r * SA + k0 + t + 4]);
                af[mt][3] = __float_as_uint(As[(r + 8) * SA + k0 + t + 4]);
            }
            #pragma unroll
            for (int nt = 0; nt < 4; ++nt) {
                int n = wn + nt * 8 + g;
                u32 bg2[2] = { __float_as_uint(Bg[(k0 + t) * SB + n]),
                               __float_as_uint(Bg[(k0 + t + 4) * SB + n]) };
                u32 bu2[2] = { __float_as_uint(Bu[(k0 + t) * SB + n]),
                               __float_as_uint(Bu[(k0 + t + 4) * SB + n]) };
                #pragma unroll
                for (int mt = 0; mt < 4; ++mt) {
                    mma8(ag[mt][nt], af[mt], bg2);
                    mma8(au[mt][nt], af[mt], bu2);
                }
            }
        }
        __syncthreads();
    }

    // epilogue: silu(g)*u*w -> act
    #pragma unroll
    for (int mt = 0; mt < 4; ++mt) {
        int l0 = wm + mt * 16 + g;
        int s0 = m0 + l0, s1 = s0 + 8;
        bool v0 = s0 < cn, v1 = s1 < cn;
        float w0 = twSm[l0], w1 = twSm[l0 + 8];
        float* o0 = actE + (size_t)s0 * Iw + n0 + wn;
        float* o1 = actE + (size_t)s1 * Iw + n0 + wn;
        #pragma unroll
        for (int nt = 0; nt < 4; ++nt) {
            int c = nt * 8 + 2 * t;
            if (v0) {
                float2 r;
                r.x = silu_f(ag[mt][nt][0]) * au[mt][nt][0] * w0;
                r.y = silu_f(ag[mt][nt][1]) * au[mt][nt][1] * w0;
                *(float2*)(o0 + c) = r;
            }
            if (v1) {
                float2 r;
                r.x = silu_f(ag[mt][nt][2]) * au[mt][nt][2] * w1;
                r.y = silu_f(ag[mt][nt][3]) * au[mt][nt][3] * w1;
                *(float2*)(o1 + c) = r;
            }
        }
    }
}

// =====================================================================
// down-proj GEMM via mma.sync tf32: CTA tile 128m x 256n
// 8 warps = 2m x 4n; warp tile 64m x 64n.
// routed: atomicAdd scatter to out rows; shared: plain store.
// =====================================================================
#define SBD 264
#define DN_DYN ((128 * SA + 32 * SBD + 128) * 4)
__global__ void __launch_bounds__(256)
down_mma(const float* __restrict__ A, const float* __restrict__ W,
         float* __restrict__ OUT, const int* __restrict__ tok,
         const int* __restrict__ cnt, int K, int accum)
{
    extern __shared__ float smf[];
    float* As = smf;                     // [128][SA]
    float* Bs = As + 128 * SA;           // [32][SBD]
    int* tokSm = (int*)(Bs + 32 * SBD);  // [128]

    int e = blockIdx.z;
    int cn = cnt ? cnt[e] : T_TOK;
    int m0 = blockIdx.y * 128;
    if (m0 >= cn) return;
    int n0 = blockIdx.x * 256;
    const float* Ae = A + (size_t)e * T_TOK * K;
    const float* Be = W + (size_t)e * K * HDIM;

    int tid = threadIdx.x;
    if (tid < 128) {
        int s = m0 + tid;
        tokSm[tid] = tok ? ((s < cn) ? tok[e * T_TOK + s] : 0) : s;
    }
    __syncthreads();

    int arow = tid >> 1, kh = (tid & 1) * 16;
    const float* aP = Ae + (size_t)(m0 + arow) * K + kh;
    int bk = tid >> 3, bc = (tid & 7) * 4;
    const float* bP = Be + (size_t)bk * HDIM + n0 + bc;

    int w = tid >> 5, lane = tid & 31;
    int g = lane >> 2, t = lane & 3;
    int wm = (w & 1) * 64, wn = (w >> 1) * 64;

    float ac[4][8][4];
    #pragma unroll
    for (int i = 0; i < 4; i++)
        #pragma unroll
        for (int j = 0; j < 8; j++)
            #pragma unroll
            for (int q = 0; q < 4; q++) ac[i][j][q] = 0.f;

    float4 pa[4], pb[8];
    #pragma unroll
    for (int i = 0; i < 4; i++) pa[i] = *(const float4*)(aP + 4 * i);
    #pragma unroll
    for (int i = 0; i < 8; i++) pb[i] = *(const float4*)(bP + 32 * i);

    const int NK = K / 32;
    for (int it = 0; it < NK; ++it) {
        #pragma unroll
        for (int i = 0; i < 4; i++)
            *(float4*)&As[arow * SA + kh + 4 * i] = tf32_4(pa[i]);
        #pragma unroll
        for (int i = 0; i < 8; i++)
            *(float4*)&Bs[bk * SBD + bc + 32 * i] = tf32_4(pb[i]);
        __syncthreads();

        if (it + 1 < NK) {
            const float* aN = aP + (it + 1) * 32;
            const float* bN = bP + (size_t)(it + 1) * 32 * HDIM;
            #pragma unroll
            for (int i = 0; i < 4; i++) pa[i] = *(const float4*)(aN + 4 * i);
            #pragma unroll
            for (int i = 0; i < 8; i++) pb[i] = *(const float4*)(bN + 32 * i);
        }

        #pragma unroll
        for (int ks = 0; ks < 4; ++ks) {
            int k0 = ks * 8;
            u32 af[4][4];
            #pragma unroll
            for (int mt = 0; mt < 4; ++mt) {
                int r = wm + mt * 16 + g;
                af[mt][0] = __float_as_uint(As[r * SA + k0 + t]);
                af[mt][1] = __float_as_uint(As[(r + 8) * SA + k0 + t]);
                af[mt][2] = __float_as_uint(As[r * SA + k0 + t + 4]);
                af[mt][3] = __float_as_uint(As[(r + 8) * SA + k0 + t + 4]);
            }
            #pragma unroll
            for (int nt = 0; nt < 8; ++nt) {
                int n = wn + nt * 8 + g;
                u32 bf2[2] = { __float_as_uint(Bs[(k0 + t) * SBD + n]),
                               __float_as_uint(Bs[(k0 + t + 4) * SBD + n]) };
                #pragma unroll
                for (int mt = 0; mt < 4; ++mt)
                    mma8(ac[mt][nt], af[mt], bf2);
            }
        }
        __syncthreads();
    }

    #pragma unroll
    for (int mt = 0; mt < 4; ++mt) {
        int l0 = wm + mt * 16 + g;
        int s0 = m0 + l0, s1 = s0 + 8;
        bool v0 = s0 < cn, v1 = s1 < cn;
        float* o0 = OUT + (size_t)tokSm[l0] * HDIM + n0 + wn;
        float* o1 = OUT + (size_t)tokSm[l0 + 8] * HDIM + n0 + wn;
        #pragma unroll
        for (int nt = 0; nt < 8; ++nt) {
            int c = nt * 8 + 2 * t;
            if (accum) {
                if (v0) { atomicAdd(o0 + c, ac[mt][nt][0]); atomicAdd(o0 + c + 1, ac[mt][nt][1]); }
                if (v1) { atomicAdd(o1 + c, ac[mt][nt][2]); atomicAdd(o1 + c + 1, ac[mt][nt][3]); }
            } else {
                if (v0) { float2 r; r.x = ac[mt][nt][0]; r.y = ac[mt][nt][1]; *(float2*)(o0 + c) = r; }
                if (v1) { float2 r; r.x = ac[mt][nt][2]; r.y = ac[mt][nt][3]; *(float2*)(o1 + c) = r; }
            }
        }
    }
}

// ---------------- launch ----------------
extern "C" void kernel_launch(void* const* d_in, const int* in_sizes, int n_in,
                              void* d_out, int out_size)
{
    const float* x    = (const float*)d_in[0];
    const float* gw   = (const float*)d_in[1];
    const float* bias = (const float*)d_in[2];
    const float* wgu  = (const float*)d_in[3];
    const float* wdn  = (const float*)d_in[4];
    const float* sgu  = (const float*)d_in[5];
    const float* sdn  = (const float*)d_in[6];
    float* out = (float*)d_out;

    void *p_cnt, *p_tok, *p_tw, *p_t4, *p_w4, *p_act, *p_acts;
    cudaGetSymbolAddress(&p_cnt,  g_cnt);
    cudaGetSymbolAddress(&p_tok,  g_tok);
    cudaGetSymbolAddress(&p_tw,   g_tw);
    cudaGetSymbolAddress(&p_t4,   g_tid4);
    cudaGetSymbolAddress(&p_w4,   g_twk4);
    cudaGetSymbolAddress(&p_act,  g_act);
    cudaGetSymbolAddress(&p_acts, g_acts);

    cudaFuncSetAttribute(gu_mma,   cudaFuncAttributeMaxDynamicSharedMemorySize, GU_DYN);
    cudaFuncSetAttribute(down_mma, cudaFuncAttributeMaxDynamicSharedMemorySize, DN_DYN);

    // 1) router + deterministic dispatch lists
    router_kernel<<<T_TOK, 128>>>(x, gw, bias, (int*)p_t4, (float*)p_w4);
    build_lists<<<1, 16>>>((const int*)p_t4, (const float*)p_w4,
                           (int*)p_cnt, (int*)p_tok, (float*)p_tw);

    // 2) gate_up + silu (tensor cores via mma.sync tf32)
    gu_mma<<<dim3(SI / 128, T_TOK / 128, 1), 256, GU_DYN>>>(
        x, sgu, (float*)p_acts, nullptr, nullptr, nullptr, SI, HDIM);
    gu_mma<<<dim3(IDIM / 128, T_TOK / 128, NEXP), 256, GU_DYN>>>(
        x, wgu, (float*)p_act, (const int*)p_tok, (const float*)p_tw,
        (const int*)p_cnt, IDIM, HDIM);

    // 3) down-proj: shared writes out (init), routed accumulates
    down_mma<<<dim3(HDIM / 256, T_TOK / 128, 1), 256, DN_DYN>>>(
        (const float*)p_acts, sdn, out, nullptr, nullptr, SI, 0);
    down_mma<<<dim3(HDIM / 256, T_TOK / 128, NEXP), 256, DN_DYN>>>(
        (const float*)p_act, wdn, out, (const int*)p_tok,
        (const int*)p_cnt, IDIM, 1);
}